// round 7
// baseline (speedup 1.0000x reference)
#include <cuda_runtime.h>
#include <cuda_bf16.h>
#include <cstdint>

#define Sdim   2048
#define Edim   256
#define KDIM   768                 // [hi | lo | hi] · [hi | hi | lo]
#define NBATCH 16
#define BM     128
#define BN     128
#define BK     32
#define NITER  (KDIM / BK)         // 24
#define NPART  (Sdim / BN)         // 16
#define NTRI   (NPART * (NPART + 1) / 2)    // 136 tile pairs per batch
#define ROWSTRIDE 80               // bytes per BK-row in smem: conflict-free ldmatrix
#define ASTAGE_BYTES (BM * ROWSTRIDE)
#define STAGE_BYTES  (2 * BM * ROWSTRIDE)   // A + B = 20480
#define NSTAGE 3
#define SMEM_MAIN (NSTAGE * STAGE_BYTES)    // 61440
#define TSTRIDE 132                          // transpose stage stride (floats)
#define SMEM_EPI  (1024 + BM * TSTRIDE * 4)  // spart + stage = 68608
#define SMEM_DYN  (SMEM_EPI > SMEM_MAIN ? SMEM_EPI : SMEM_MAIN)

__device__ __nv_bfloat16 g_a[(size_t)NBATCH * Sdim * KDIM];
__device__ __nv_bfloat16 g_b[(size_t)NBATCH * Sdim * KDIM];
__device__ float         g_sq[NBATCH * Sdim];
__device__ float         g_part[(size_t)NBATCH * Sdim * NPART];
__device__ int           g_ready[NBATCH * NPART];

__device__ __forceinline__ uint32_t smem_to_u32(const void* p) {
    uint32_t a;
    asm("{ .reg .u64 t; cvta.to.shared.u64 t, %1; cvt.u32.u64 %0, t; }" : "=r"(a) : "l"(p));
    return a;
}

#define CP16(dst, src) \
    asm volatile("cp.async.cg.shared.global [%0], [%1], 16;" :: "r"(dst), "l"(src) : "memory")
#define CP_COMMIT() asm volatile("cp.async.commit_group;" ::: "memory")

__device__ __forceinline__ void ldmx4(uint32_t* r, uint32_t addr) {
    asm volatile("ldmatrix.sync.aligned.m8n8.x4.shared.b16 {%0,%1,%2,%3}, [%4];"
                 : "=r"(r[0]), "=r"(r[1]), "=r"(r[2]), "=r"(r[3]) : "r"(addr));
}
__device__ __forceinline__ void mma16816(float* d, const uint32_t* a, const uint32_t* b) {
    asm volatile("mma.sync.aligned.m16n8k16.row.col.f32.bf16.bf16.f32 "
                 "{%0,%1,%2,%3}, {%4,%5,%6,%7}, {%8,%9}, {%0,%1,%2,%3};"
                 : "+f"(d[0]), "+f"(d[1]), "+f"(d[2]), "+f"(d[3])
                 : "r"(a[0]), "r"(a[1]), "r"(a[2]), "r"(a[3]), "r"(b[0]), "r"(b[1]));
}

// ================= Kernel 1: bf16 hi/lo split + sq norms (+ counter reset) =================
__global__ __launch_bounds__(256) void split_kernel(const float* __restrict__ x) {
    if (blockIdx.x == 0 && threadIdx.x < NBATCH * NPART) g_ready[threadIdx.x] = 0;

    int row  = blockIdx.x * 8 + (threadIdx.x >> 5);
    int lane = threadIdx.x & 31;
    const float4* xr = reinterpret_cast<const float4*>(x + (size_t)row * Edim);
    float4 v0 = xr[lane], v1 = xr[lane + 32];
    float vv[8] = {v0.x, v0.y, v0.z, v0.w, v1.x, v1.y, v1.z, v1.w};

    float s = 0.f;
    uint32_t ph[4], pl[4];
    #pragma unroll
    for (int q = 0; q < 4; ++q) {
        __nv_bfloat16 h0 = __float2bfloat16(vv[2*q]),   h1 = __float2bfloat16(vv[2*q+1]);
        __nv_bfloat16 l0 = __float2bfloat16(vv[2*q]   - __bfloat162float(h0));
        __nv_bfloat16 l1 = __float2bfloat16(vv[2*q+1] - __bfloat162float(h1));
        __nv_bfloat162 hp = __halves2bfloat162(h0, h1), lp = __halves2bfloat162(l0, l1);
        ph[q] = *reinterpret_cast<uint32_t*>(&hp);
        pl[q] = *reinterpret_cast<uint32_t*>(&lp);
        s += vv[2*q]*vv[2*q] + vv[2*q+1]*vv[2*q+1];
    }
    uint2 hi0 = make_uint2(ph[0], ph[1]), hi1 = make_uint2(ph[2], ph[3]);
    uint2 lo0 = make_uint2(pl[0], pl[1]), lo1 = make_uint2(pl[2], pl[3]);

    __nv_bfloat16* A = g_a + (size_t)row * KDIM;
    __nv_bfloat16* B = g_b + (size_t)row * KDIM;
    int c = 4 * lane;
    *reinterpret_cast<uint2*>(A +       c) = hi0;  *reinterpret_cast<uint2*>(A + 128 + c) = hi1;
    *reinterpret_cast<uint2*>(A + 256 + c) = lo0;  *reinterpret_cast<uint2*>(A + 384 + c) = lo1;
    *reinterpret_cast<uint2*>(A + 512 + c) = hi0;  *reinterpret_cast<uint2*>(A + 640 + c) = hi1;
    *reinterpret_cast<uint2*>(B +       c) = hi0;  *reinterpret_cast<uint2*>(B + 128 + c) = hi1;
    *reinterpret_cast<uint2*>(B + 256 + c) = hi0;  *reinterpret_cast<uint2*>(B + 384 + c) = hi1;
    *reinterpret_cast<uint2*>(B + 512 + c) = lo0;  *reinterpret_cast<uint2*>(B + 640 + c) = lo1;

    #pragma unroll
    for (int o = 16; o; o >>= 1) s += __shfl_xor_sync(0xffffffffu, s, o);
    if (lane == 0) g_sq[row] = s;
}

// ================= Kernel 2: HMMA gram + exp + fused normalization =================
__global__ __launch_bounds__(256) void gemm_kernel(float* __restrict__ out) {
    extern __shared__ char smem[];
    uint32_t sbase = smem_to_u32(smem);
    const int tid = threadIdx.x, l = tid & 31, wid = tid >> 5;
    const int warp_m = wid & 3, warp_n = wid >> 2;     // 4 x 2 warps, 32x64 tiles
    const int b = blockIdx.z;

    int by = 0, rem = blockIdx.x;
    while (rem >= NPART - by) { rem -= NPART - by; ++by; }
    const int bx = by + rem;
    const bool offdiag = (bx != by);

    const __nv_bfloat16* Ag = g_a + ((size_t)b * Sdim + by * BM) * KDIM;
    const __nv_bfloat16* Bg = g_b + ((size_t)b * Sdim + bx * BN) * KDIM;

    const int crow  = tid >> 1;
    const int ccol0 = (tid & 1) * 2;
    const char* srcA = (const char*)(Ag + (size_t)crow * KDIM + ccol0 * 8);
    const char* srcB = (const char*)(Bg + (size_t)crow * KDIM + ccol0 * 8);
    const uint32_t dA = crow * ROWSTRIDE + ccol0 * 16;
    const uint32_t dB = dA + ASTAGE_BYTES;

    uint32_t aoff[2];
    #pragma unroll
    for (int m = 0; m < 2; ++m)
        aoff[m] = (warp_m * 32 + m * 16 + (l & 15)) * ROWSTRIDE + (l >> 4) * 16;
    uint32_t boff[4];
    {
        int grp = l >> 3, nof = (grp >> 1) * 8 + (l & 7), cof = (grp & 1) * 16;
        #pragma unroll
        for (int p = 0; p < 4; ++p)
            boff[p] = ASTAGE_BYTES + (warp_n * 64 + p * 16 + nof) * ROWSTRIDE + cof;
    }

    #pragma unroll
    for (int it = 0; it < 2; ++it) {
        uint32_t so = sbase + it * STAGE_BYTES;
        const char* sa = srcA + it * 64;
        const char* sb = srcB + it * 64;
        CP16(so + dA, sa); CP16(so + dA + 16, sa + 16);
        CP16(so + dB, sb); CP16(so + dB + 16, sb + 16);
        CP_COMMIT();
    }

    float d[2][8][4];
    #pragma unroll
    for (int m = 0; m < 2; ++m)
        #pragma unroll
        for (int n = 0; n < 8; ++n)
            #pragma unroll
            for (int q = 0; q < 4; ++q) d[m][n][q] = 0.f;

    for (int it = 0; it < NITER; ++it) {
        if (it == NITER - 1) asm volatile("cp.async.wait_group 0;" ::: "memory");
        else                 asm volatile("cp.async.wait_group 1;" ::: "memory");
        __syncthreads();
        uint32_t sb = sbase + (it % 3) * STAGE_BYTES;
        #pragma unroll
        for (int ks = 0; ks < 2; ++ks) {
            uint32_t a[2][4], bb[8][2];
            #pragma unroll
            for (int m = 0; m < 2; ++m) ldmx4(a[m], sb + aoff[m] + ks * 32);
            #pragma unroll
            for (int p = 0; p < 4; ++p) {
                uint32_t r[4];
                ldmx4(r, sb + boff[p] + ks * 32);
                bb[2*p][0] = r[0]; bb[2*p][1] = r[1];
                bb[2*p+1][0] = r[2]; bb[2*p+1][1] = r[3];
            }
            #pragma unroll
            for (int m = 0; m < 2; ++m)
                #pragma unroll
                for (int n = 0; n < 8; ++n) mma16816(d[m][n], a[m], bb[n]);
        }
        if (it + 2 < NITER) {
            uint32_t so = sbase + ((it + 2) % 3) * STAGE_BYTES;
            const char* sa = srcA + (it + 2) * 64;
            const char* sb2 = srcB + (it + 2) * 64;
            CP16(so + dA, sa); CP16(so + dA + 16, sa + 16);
            CP16(so + dB, sb2); CP16(so + dB + 16, sb2 + 16);
            CP_COMMIT();
        }
    }

    // ---- epilogue ----
    __syncthreads();
    float* spart  = reinterpret_cast<float*>(smem);          // [128][2] row partials
    float* stagef = reinterpret_cast<float*>(smem + 1024);   // transpose stage

    float sqi[4];
    #pragma unroll
    for (int m = 0; m < 2; ++m)
        #pragma unroll
        for (int h = 0; h < 2; ++h)
            sqi[2*m+h] = g_sq[b * Sdim + by * BM + warp_m * 32 + m * 16 + h * 8 + (l >> 2)];
    float2 sqj[8];
    #pragma unroll
    for (int n = 0; n < 8; ++n)
        sqj[n] = *reinterpret_cast<const float2*>(
            &g_sq[b * Sdim + bx * BN + warp_n * 64 + n * 8 + 2 * (l & 3)]);

    float* ob = out + ((size_t)b * Sdim + by * BM) * Sdim + bx * BN;
    float rs[4] = {0.f, 0.f, 0.f, 0.f};
    #pragma unroll
    for (int m = 0; m < 2; ++m) {
        #pragma unroll
        for (int h = 0; h < 2; ++h) {
            int row = warp_m * 32 + m * 16 + h * 8 + (l >> 2);
            float bi = -0.0625f * sqi[2*m+h];
            float* orow = ob + (size_t)row * Sdim + warp_n * 64 + 2 * (l & 3);
            float acc = 0.f;
            #pragma unroll
            for (int n = 0; n < 8; ++n) {
                float p0 = __expf(fmaf(d[m][n][2*h],     0.125f, fmaf(sqj[n].x, -0.0625f, bi)));
                float p1 = __expf(fmaf(d[m][n][2*h + 1], 0.125f, fmaf(sqj[n].y, -0.0625f, bi)));
                acc += p0 + p1;
                *reinterpret_cast<float2*>(orow + n * 8) = make_float2(p0, p1);
                if (offdiag) {
                    int col = warp_n * 64 + n * 8 + 2 * (l & 3);
                    stagef[(col)     * TSTRIDE + row] = p0;
                    stagef[(col + 1) * TSTRIDE + row] = p1;
                }
            }
            rs[2*m+h] = acc;
        }
    }
    #pragma unroll
    for (int i = 0; i < 4; ++i) {
        rs[i] += __shfl_xor_sync(0xffffffffu, rs[i], 1);
        rs[i] += __shfl_xor_sync(0xffffffffu, rs[i], 2);
    }
    if ((l & 3) == 0) {
        #pragma unroll
        for (int m = 0; m < 2; ++m)
            #pragma unroll
            for (int h = 0; h < 2; ++h) {
                int row = warp_m * 32 + m * 16 + h * 8 + (l >> 2);
                spart[row * 2 + warp_n] = rs[2*m+h];
            }
    }
    __syncthreads();
    if (tid < BM)
        g_part[((size_t)b * Sdim + by * BM + tid) * NPART + bx] =
            spart[tid * 2] + spart[tid * 2 + 1];

    if (offdiag) {
        {
            int j = tid >> 1, base = (tid & 1) * 64;
            const float* sp = stagef + j * TSTRIDE + base;
            float s = 0.f;
            #pragma unroll 16
            for (int k = 0; k < 64; ++k) s += sp[k];
            s += __shfl_xor_sync(0xffffffffu, s, 1);
            if (!(tid & 1))
                g_part[((size_t)b * Sdim + bx * BN + j) * NPART + by] = s;
        }
        float* obT = out + ((size_t)b * Sdim + bx * BN) * Sdim + by * BM;
        const int jrow = tid >> 6;
        const int c    = 2 * (tid & 63);
        #pragma unroll 8
        for (int it2 = 0; it2 < 32; ++it2) {
            int j = it2 * 4 + jrow;
            float2 v = *reinterpret_cast<const float2*>(&stagef[j * TSTRIDE + c]);
            *reinterpret_cast<float2*>(&obT[(size_t)j * Sdim + c]) = v;
        }
    }

    // ---- fused normalization: last contributor to a row-block normalizes it ----
    __syncthreads();
    int* flags = reinterpret_cast<int*>(smem);     // reuse smem: [0]=do_by, [1]=do_bx
    __threadfence();                               // release: tile + partials visible
    if (tid == 0) {
        flags[0] = (atomicAdd(&g_ready[b * NPART + by], 1) == NPART - 1);
        flags[1] = offdiag ? (atomicAdd(&g_ready[b * NPART + bx], 1) == NPART - 1) : 0;
    }
    __syncthreads();
    const int do_by = flags[0], do_bx = flags[1];
    if (do_by | do_bx) __threadfence();            // acquire: see other CTAs' writes
    __syncthreads();
    float* sinv = reinterpret_cast<float*>(smem);  // [128]

    #pragma unroll
    for (int pass = 0; pass < 2; ++pass) {
        int go = pass == 0 ? do_by : do_bx;
        int rb = pass == 0 ? by : bx;
        if (!go) continue;
        if (tid < BM) {
            const float* pp = &g_part[((size_t)b * Sdim + rb * BM + tid) * NPART];
            float s = 0.f;
            #pragma unroll
            for (int k = 0; k < NPART; ++k) s += pp[k];
            sinv[tid] = 1.0f / s;
        }
        __syncthreads();
        float* obase = out + ((size_t)b * Sdim + rb * BM) * Sdim;
        // warp w handles rows w*16 .. w*16+15
        #pragma unroll 2
        for (int rr = 0; rr < 16; ++rr) {
            int r = (tid >> 5) * 16 + rr;
            float inv = sinv[r];
            float4* p4 = reinterpret_cast<float4*>(obase + (size_t)r * Sdim);
            #pragma unroll 4
            for (int k = 0; k < 16; ++k) {
                float4 v = p4[l + 32 * k];
                v.x *= inv; v.y *= inv; v.z *= inv; v.w *= inv;
                p4[l + 32 * k] = v;
            }
        }
        __syncthreads();
    }
}

extern "C" void kernel_launch(void* const* d_in, const int* in_sizes, int n_in,
                              void* d_out, int out_size) {
    const float* x  = (const float*)d_in[0];
    float*       out = (float*)d_out;

    cudaFuncSetAttribute(gemm_kernel, cudaFuncAttributeMaxDynamicSharedMemorySize, SMEM_DYN);

    split_kernel<<<NBATCH * Sdim / 8, 256>>>(x);
    gemm_kernel<<<dim3(NTRI, 1, NBATCH), 256, SMEM_DYN>>>(out);
}

// round 8
// speedup vs baseline: 1.0749x; 1.0749x over previous
#include <cuda_runtime.h>
#include <cuda_bf16.h>
#include <cstdint>

#define Sdim   2048
#define Edim   256
#define KDIM   768                 // [hi | lo | hi] · [hi | hi | lo]
#define NBATCH 16
#define BM     128
#define BN     128
#define BK     32
#define NITER  (KDIM / BK)         // 24
#define NPART  (Sdim / BN)         // 16
#define NTRI   (NPART * (NPART + 1) / 2)    // 136 tile pairs per batch
#define ROWSTRIDE 80               // bytes per BK-row in smem: conflict-free ldmatrix
#define ASTAGE_BYTES (BM * ROWSTRIDE)
#define STAGE_BYTES  (2 * BM * ROWSTRIDE)   // A + B = 20480
#define NSTAGE 3
#define SMEM_MAIN (NSTAGE * STAGE_BYTES)    // 61440
#define TSTRIDE 132                          // transpose stage stride (floats)
#define SMEM_EPI  (1024 + BM * TSTRIDE * 4)  // spart + stage = 68608
#define SMEM_DYN  (SMEM_EPI > SMEM_MAIN ? SMEM_EPI : SMEM_MAIN)

__device__ __nv_bfloat16 g_a[(size_t)NBATCH * Sdim * KDIM];
__device__ __nv_bfloat16 g_b[(size_t)NBATCH * Sdim * KDIM];
__device__ float         g_sq[NBATCH * Sdim];
__device__ float         g_part[(size_t)NBATCH * Sdim * NPART];

__device__ __forceinline__ uint32_t smem_to_u32(const void* p) {
    uint32_t a;
    asm("{ .reg .u64 t; cvta.to.shared.u64 t, %1; cvt.u32.u64 %0, t; }" : "=r"(a) : "l"(p));
    return a;
}

#define CP16(dst, src) \
    asm volatile("cp.async.cg.shared.global [%0], [%1], 16;" :: "r"(dst), "l"(src) : "memory")
#define CP_COMMIT() asm volatile("cp.async.commit_group;" ::: "memory")

__device__ __forceinline__ void ldmx4(uint32_t* r, uint32_t addr) {
    asm volatile("ldmatrix.sync.aligned.m8n8.x4.shared.b16 {%0,%1,%2,%3}, [%4];"
                 : "=r"(r[0]), "=r"(r[1]), "=r"(r[2]), "=r"(r[3]) : "r"(addr));
}
__device__ __forceinline__ void mma16816(float* d, const uint32_t* a, const uint32_t* b) {
    asm volatile("mma.sync.aligned.m16n8k16.row.col.f32.bf16.bf16.f32 "
                 "{%0,%1,%2,%3}, {%4,%5,%6,%7}, {%8,%9}, {%0,%1,%2,%3};"
                 : "+f"(d[0]), "+f"(d[1]), "+f"(d[2]), "+f"(d[3])
                 : "r"(a[0]), "r"(a[1]), "r"(a[2]), "r"(a[3]), "r"(b[0]), "r"(b[1]));
}

// ================= Kernel 1: bf16 hi/lo split + sq norms =================
__global__ __launch_bounds__(256) void split_kernel(const float* __restrict__ x) {
    int row  = blockIdx.x * 8 + (threadIdx.x >> 5);
    int lane = threadIdx.x & 31;
    const float4* xr = reinterpret_cast<const float4*>(x + (size_t)row * Edim);
    float4 v0 = xr[lane], v1 = xr[lane + 32];
    float vv[8] = {v0.x, v0.y, v0.z, v0.w, v1.x, v1.y, v1.z, v1.w};

    float s = 0.f;
    uint32_t ph[4], pl[4];
    #pragma unroll
    for (int q = 0; q < 4; ++q) {
        __nv_bfloat16 h0 = __float2bfloat16(vv[2*q]),   h1 = __float2bfloat16(vv[2*q+1]);
        __nv_bfloat16 l0 = __float2bfloat16(vv[2*q]   - __bfloat162float(h0));
        __nv_bfloat16 l1 = __float2bfloat16(vv[2*q+1] - __bfloat162float(h1));
        __nv_bfloat162 hp = __halves2bfloat162(h0, h1), lp = __halves2bfloat162(l0, l1);
        ph[q] = *reinterpret_cast<uint32_t*>(&hp);
        pl[q] = *reinterpret_cast<uint32_t*>(&lp);
        s += vv[2*q]*vv[2*q] + vv[2*q+1]*vv[2*q+1];
    }
    uint2 hi0 = make_uint2(ph[0], ph[1]), hi1 = make_uint2(ph[2], ph[3]);
    uint2 lo0 = make_uint2(pl[0], pl[1]), lo1 = make_uint2(pl[2], pl[3]);

    __nv_bfloat16* A = g_a + (size_t)row * KDIM;
    __nv_bfloat16* B = g_b + (size_t)row * KDIM;
    int c = 4 * lane;
    *reinterpret_cast<uint2*>(A +       c) = hi0;  *reinterpret_cast<uint2*>(A + 128 + c) = hi1;
    *reinterpret_cast<uint2*>(A + 256 + c) = lo0;  *reinterpret_cast<uint2*>(A + 384 + c) = lo1;
    *reinterpret_cast<uint2*>(A + 512 + c) = hi0;  *reinterpret_cast<uint2*>(A + 640 + c) = hi1;
    *reinterpret_cast<uint2*>(B +       c) = hi0;  *reinterpret_cast<uint2*>(B + 128 + c) = hi1;
    *reinterpret_cast<uint2*>(B + 256 + c) = hi0;  *reinterpret_cast<uint2*>(B + 384 + c) = hi1;
    *reinterpret_cast<uint2*>(B + 512 + c) = lo0;  *reinterpret_cast<uint2*>(B + 640 + c) = lo1;

    #pragma unroll
    for (int o = 16; o; o >>= 1) s += __shfl_xor_sync(0xffffffffu, s, o);
    if (lane == 0) g_sq[row] = s;
}

// ================= Kernel 2: HMMA gram + exp, upper-triangular tiles =================
__global__ __launch_bounds__(256, 2) void gemm_kernel(float* __restrict__ out) {
    extern __shared__ char smem[];
    uint32_t sbase = smem_to_u32(smem);
    const int tid = threadIdx.x, l = tid & 31, wid = tid >> 5;
    const int warp_m = wid & 3, warp_n = wid >> 2;     // 4 x 2 warps, 32x64 tiles
    const int b = blockIdx.z;

    int by = 0, rem = blockIdx.x;
    while (rem >= NPART - by) { rem -= NPART - by; ++by; }
    const int bx = by + rem;
    const bool offdiag = (bx != by);

    const __nv_bfloat16* Ag = g_a + ((size_t)b * Sdim + by * BM) * KDIM;
    const __nv_bfloat16* Bg = g_b + ((size_t)b * Sdim + bx * BN) * KDIM;

    const int crow  = tid >> 1;
    const int ccol0 = (tid & 1) * 2;
    const char* srcA = (const char*)(Ag + (size_t)crow * KDIM + ccol0 * 8);
    const char* srcB = (const char*)(Bg + (size_t)crow * KDIM + ccol0 * 8);
    const uint32_t dA = crow * ROWSTRIDE + ccol0 * 16;
    const uint32_t dB = dA + ASTAGE_BYTES;

    uint32_t aoff[2];
    #pragma unroll
    for (int m = 0; m < 2; ++m)
        aoff[m] = (warp_m * 32 + m * 16 + (l & 15)) * ROWSTRIDE + (l >> 4) * 16;
    uint32_t boff[4];
    {
        int grp = l >> 3, nof = (grp >> 1) * 8 + (l & 7), cof = (grp & 1) * 16;
        #pragma unroll
        for (int p = 0; p < 4; ++p)
            boff[p] = ASTAGE_BYTES + (warp_n * 64 + p * 16 + nof) * ROWSTRIDE + cof;
    }

    #pragma unroll
    for (int it = 0; it < 2; ++it) {
        uint32_t so = sbase + it * STAGE_BYTES;
        const char* sa = srcA + it * 64;
        const char* sb = srcB + it * 64;
        CP16(so + dA, sa); CP16(so + dA + 16, sa + 16);
        CP16(so + dB, sb); CP16(so + dB + 16, sb + 16);
        CP_COMMIT();
    }

    float d[2][8][4];
    #pragma unroll
    for (int m = 0; m < 2; ++m)
        #pragma unroll
        for (int n = 0; n < 8; ++n)
            #pragma unroll
            for (int q = 0; q < 4; ++q) d[m][n][q] = 0.f;

    for (int it = 0; it < NITER; ++it) {
        if (it == NITER - 1) asm volatile("cp.async.wait_group 0;" ::: "memory");
        else                 asm volatile("cp.async.wait_group 1;" ::: "memory");
        __syncthreads();
        uint32_t sb = sbase + (it % 3) * STAGE_BYTES;

        // ---- hoist ALL fragment loads (both k-halves) ahead of all MMAs ----
        uint32_t a0[2][4], a1[2][4], b0[8][2], b1[8][2];
        #pragma unroll
        for (int m = 0; m < 2; ++m) ldmx4(a0[m], sb + aoff[m]);
        #pragma unroll
        for (int p = 0; p < 4; ++p) {
            uint32_t r[4];
            ldmx4(r, sb + boff[p]);
            b0[2*p][0] = r[0]; b0[2*p][1] = r[1];
            b0[2*p+1][0] = r[2]; b0[2*p+1][1] = r[3];
        }
        #pragma unroll
        for (int m = 0; m < 2; ++m) ldmx4(a1[m], sb + aoff[m] + 32);
        #pragma unroll
        for (int p = 0; p < 4; ++p) {
            uint32_t r[4];
            ldmx4(r, sb + boff[p] + 32);
            b1[2*p][0] = r[0]; b1[2*p][1] = r[1];
            b1[2*p+1][0] = r[2]; b1[2*p+1][1] = r[3];
        }

        // prefetch next stage while fragments are in flight
        if (it + 2 < NITER) {
            uint32_t so = sbase + ((it + 2) % 3) * STAGE_BYTES;
            const char* sa = srcA + (it + 2) * 64;
            const char* sb2 = srcB + (it + 2) * 64;
            CP16(so + dA, sa); CP16(so + dA + 16, sa + 16);
            CP16(so + dB, sb2); CP16(so + dB + 16, sb2 + 16);
            CP_COMMIT();
        }

        #pragma unroll
        for (int m = 0; m < 2; ++m)
            #pragma unroll
            for (int n = 0; n < 8; ++n) mma16816(d[m][n], a0[m], b0[n]);
        #pragma unroll
        for (int m = 0; m < 2; ++m)
            #pragma unroll
            for (int n = 0; n < 8; ++n) mma16816(d[m][n], a1[m], b1[n]);
    }

    // ---- epilogue ----
    __syncthreads();
    float* spart  = reinterpret_cast<float*>(smem);          // [128][2] row partials
    float* stagef = reinterpret_cast<float*>(smem + 1024);   // transpose stage

    float sqi[4];
    #pragma unroll
    for (int m = 0; m < 2; ++m)
        #pragma unroll
        for (int h = 0; h < 2; ++h)
            sqi[2*m+h] = g_sq[b * Sdim + by * BM + warp_m * 32 + m * 16 + h * 8 + (l >> 2)];
    float2 sqj[8];
    #pragma unroll
    for (int n = 0; n < 8; ++n)
        sqj[n] = *reinterpret_cast<const float2*>(
            &g_sq[b * Sdim + bx * BN + warp_n * 64 + n * 8 + 2 * (l & 3)]);

    float* ob = out + ((size_t)b * Sdim + by * BM) * Sdim + bx * BN;
    float rs[4] = {0.f, 0.f, 0.f, 0.f};
    #pragma unroll
    for (int m = 0; m < 2; ++m) {
        #pragma unroll
        for (int h = 0; h < 2; ++h) {
            int row = warp_m * 32 + m * 16 + h * 8 + (l >> 2);
            float bi = -0.0625f * sqi[2*m+h];
            float* orow = ob + (size_t)row * Sdim + warp_n * 64 + 2 * (l & 3);
            float acc = 0.f;
            #pragma unroll
            for (int n = 0; n < 8; ++n) {
                float p0 = __expf(fmaf(d[m][n][2*h],     0.125f, fmaf(sqj[n].x, -0.0625f, bi)));
                float p1 = __expf(fmaf(d[m][n][2*h + 1], 0.125f, fmaf(sqj[n].y, -0.0625f, bi)));
                acc += p0 + p1;
                *reinterpret_cast<float2*>(orow + n * 8) = make_float2(p0, p1);
                if (offdiag) {
                    int col = warp_n * 64 + n * 8 + 2 * (l & 3);
                    stagef[(col)     * TSTRIDE + row] = p0;
                    stagef[(col + 1) * TSTRIDE + row] = p1;
                }
            }
            rs[2*m+h] = acc;
        }
    }
    #pragma unroll
    for (int i = 0; i < 4; ++i) {
        rs[i] += __shfl_xor_sync(0xffffffffu, rs[i], 1);
        rs[i] += __shfl_xor_sync(0xffffffffu, rs[i], 2);
    }
    if ((l & 3) == 0) {
        #pragma unroll
        for (int m = 0; m < 2; ++m)
            #pragma unroll
            for (int h = 0; h < 2; ++h) {
                int row = warp_m * 32 + m * 16 + h * 8 + (l >> 2);
                spart[row * 2 + warp_n] = rs[2*m+h];
            }
    }
    __syncthreads();
    if (tid < BM)
        g_part[((size_t)b * Sdim + by * BM + tid) * NPART + bx] =
            spart[tid * 2] + spart[tid * 2 + 1];

    if (offdiag) {
        {
            int j = tid >> 1, base = (tid & 1) * 64;
            const float* sp = stagef + j * TSTRIDE + base;
            float s = 0.f;
            #pragma unroll 16
            for (int k = 0; k < 64; ++k) s += sp[k];
            s += __shfl_xor_sync(0xffffffffu, s, 1);
            if (!(tid & 1))
                g_part[((size_t)b * Sdim + bx * BN + j) * NPART + by] = s;
        }
        float* obT = out + ((size_t)b * Sdim + bx * BN) * Sdim + by * BM;
        const int jrow = tid >> 6;
        const int c    = 2 * (tid & 63);
        #pragma unroll 8
        for (int it2 = 0; it2 < 32; ++it2) {
            int j = it2 * 4 + jrow;
            float2 v = *reinterpret_cast<const float2*>(&stagef[j * TSTRIDE + c]);
            *reinterpret_cast<float2*>(&obT[(size_t)j * Sdim + c]) = v;
        }
    }
}

// ================= Kernel 3: normalize =================
__global__ __launch_bounds__(256) void norm_kernel(float* __restrict__ out) {
    int w = threadIdx.x >> 5, l = threadIdx.x & 31;
    size_t row = (size_t)blockIdx.x * 8 + w;
    float v = (l < NPART) ? g_part[row * NPART + l] : 0.f;
    #pragma unroll
    for (int o = 16; o; o >>= 1) v += __shfl_xor_sync(0xffffffffu, v, o);
    float inv = 1.0f / v;
    float4* o4 = reinterpret_cast<float4*>(out + row * Sdim);
    #pragma unroll 4
    for (int k = 0; k < Sdim / 4 / 32; ++k) {
        float4 t = o4[l + 32 * k];
        t.x *= inv; t.y *= inv; t.z *= inv; t.w *= inv;
        o4[l + 32 * k] = t;
    }
}

extern "C" void kernel_launch(void* const* d_in, const int* in_sizes, int n_in,
                              void* d_out, int out_size) {
    const float* x  = (const float*)d_in[0];
    float*       out = (float*)d_out;

    cudaFuncSetAttribute(gemm_kernel, cudaFuncAttributeMaxDynamicSharedMemorySize, SMEM_DYN);

    split_kernel<<<NBATCH * Sdim / 8, 256>>>(x);
    gemm_kernel<<<dim3(NTRI, 1, NBATCH), 256, SMEM_DYN>>>(out);
    norm_kernel<<<NBATCH * Sdim / 8, 256>>>(out);
}

// round 10
// speedup vs baseline: 1.0884x; 1.0126x over previous
#include <cuda_runtime.h>
#include <cuda_bf16.h>
#include <cstdint>

#define Sdim   2048
#define Edim   256
#define KDIM   768                 // [hi | lo | hi] · [hi | hi | lo]
#define NBATCH 16
#define BM     128
#define BN     128
#define BK     32
#define NITER  (KDIM / BK)         // 24
#define NPART  (Sdim / BN)         // 16
#define NTRI   (NPART * (NPART + 1) / 2)    // 136 tile pairs per batch
#define ROWSTRIDE 80               // bytes per BK-row in smem: conflict-free ldmatrix
#define ASTAGE_BYTES (BM * ROWSTRIDE)
#define STAGE_BYTES  (2 * BM * ROWSTRIDE)   // A + B = 20480
#define NSTAGE 3
#define SMEM_MAIN (NSTAGE * STAGE_BYTES)    // 61440
#define S2 129                               // norm2 transpose stage stride (floats)
#define NORM_SMEM (1024 + BM * S2 * 4)       // 1024 + 66048

__device__ __nv_bfloat16 g_a[(size_t)NBATCH * Sdim * KDIM];
__device__ __nv_bfloat16 g_b[(size_t)NBATCH * Sdim * KDIM];
__device__ float         g_sq[NBATCH * Sdim];
__device__ float         g_part[(size_t)NBATCH * Sdim * NPART];

__device__ __forceinline__ uint32_t smem_to_u32(const void* p) {
    uint32_t a;
    asm("{ .reg .u64 t; cvta.to.shared.u64 t, %1; cvt.u32.u64 %0, t; }" : "=r"(a) : "l"(p));
    return a;
}

#define CP16(dst, src) \
    asm volatile("cp.async.cg.shared.global [%0], [%1], 16;" :: "r"(dst), "l"(src) : "memory")
#define CP_COMMIT() asm volatile("cp.async.commit_group;" ::: "memory")

__device__ __forceinline__ void ldmx4(uint32_t* r, uint32_t addr) {
    asm volatile("ldmatrix.sync.aligned.m8n8.x4.shared.b16 {%0,%1,%2,%3}, [%4];"
                 : "=r"(r[0]), "=r"(r[1]), "=r"(r[2]), "=r"(r[3]) : "r"(addr));
}
__device__ __forceinline__ void mma16816(float* d, const uint32_t* a, const uint32_t* b) {
    asm volatile("mma.sync.aligned.m16n8k16.row.col.f32.bf16.bf16.f32 "
                 "{%0,%1,%2,%3}, {%4,%5,%6,%7}, {%8,%9}, {%0,%1,%2,%3};"
                 : "+f"(d[0]), "+f"(d[1]), "+f"(d[2]), "+f"(d[3])
                 : "r"(a[0]), "r"(a[1]), "r"(a[2]), "r"(a[3]), "r"(b[0]), "r"(b[1]));
}

// ================= Kernel 1: bf16 hi/lo split + sq norms =================
__global__ __launch_bounds__(256) void split_kernel(const float* __restrict__ x) {
    int row  = blockIdx.x * 8 + (threadIdx.x >> 5);
    int lane = threadIdx.x & 31;
    const float4* xr = reinterpret_cast<const float4*>(x + (size_t)row * Edim);
    float4 v0 = xr[lane], v1 = xr[lane + 32];
    float vv[8] = {v0.x, v0.y, v0.z, v0.w, v1.x, v1.y, v1.z, v1.w};

    float s = 0.f;
    uint32_t ph[4], pl[4];
    #pragma unroll
    for (int q = 0; q < 4; ++q) {
        __nv_bfloat16 h0 = __float2bfloat16(vv[2*q]),   h1 = __float2bfloat16(vv[2*q+1]);
        __nv_bfloat16 l0 = __float2bfloat16(vv[2*q]   - __bfloat162float(h0));
        __nv_bfloat16 l1 = __float2bfloat16(vv[2*q+1] - __bfloat162float(h1));
        __nv_bfloat162 hp = __halves2bfloat162(h0, h1), lp = __halves2bfloat162(l0, l1);
        ph[q] = *reinterpret_cast<uint32_t*>(&hp);
        pl[q] = *reinterpret_cast<uint32_t*>(&lp);
        s += vv[2*q]*vv[2*q] + vv[2*q+1]*vv[2*q+1];
    }
    uint2 hi0 = make_uint2(ph[0], ph[1]), hi1 = make_uint2(ph[2], ph[3]);
    uint2 lo0 = make_uint2(pl[0], pl[1]), lo1 = make_uint2(pl[2], pl[3]);

    __nv_bfloat16* A = g_a + (size_t)row * KDIM;
    __nv_bfloat16* B = g_b + (size_t)row * KDIM;
    int c = 4 * lane;
    *reinterpret_cast<uint2*>(A +       c) = hi0;  *reinterpret_cast<uint2*>(A + 128 + c) = hi1;
    *reinterpret_cast<uint2*>(A + 256 + c) = lo0;  *reinterpret_cast<uint2*>(A + 384 + c) = lo1;
    *reinterpret_cast<uint2*>(A + 512 + c) = hi0;  *reinterpret_cast<uint2*>(A + 640 + c) = hi1;
    *reinterpret_cast<uint2*>(B +       c) = hi0;  *reinterpret_cast<uint2*>(B + 128 + c) = hi1;
    *reinterpret_cast<uint2*>(B + 256 + c) = hi0;  *reinterpret_cast<uint2*>(B + 384 + c) = hi1;
    *reinterpret_cast<uint2*>(B + 512 + c) = lo0;  *reinterpret_cast<uint2*>(B + 640 + c) = lo1;

    #pragma unroll
    for (int o = 16; o; o >>= 1) s += __shfl_xor_sync(0xffffffffu, s, o);
    if (lane == 0) g_sq[row] = s;
}

// ================= Kernel 2: HMMA gram + exp, upper-tri tiles only =================
__global__ __launch_bounds__(256, 2) void gemm_kernel(float* __restrict__ out) {
    extern __shared__ char smem[];
    uint32_t sbase = smem_to_u32(smem);
    const int tid = threadIdx.x, l = tid & 31, wid = tid >> 5;
    const int warp_m = wid & 3, warp_n = wid >> 2;     // 4 x 2 warps, 32x64 tiles
    const int b = blockIdx.z;

    int by = 0, rem = blockIdx.x;
    while (rem >= NPART - by) { rem -= NPART - by; ++by; }
    const int bx = by + rem;
    const bool offdiag = (bx != by);

    const __nv_bfloat16* Ag = g_a + ((size_t)b * Sdim + by * BM) * KDIM;
    const __nv_bfloat16* Bg = g_b + ((size_t)b * Sdim + bx * BN) * KDIM;

    const int crow  = tid >> 1;
    const int ccol0 = (tid & 1) * 2;
    const char* srcA = (const char*)(Ag + (size_t)crow * KDIM + ccol0 * 8);
    const char* srcB = (const char*)(Bg + (size_t)crow * KDIM + ccol0 * 8);
    const uint32_t dA = crow * ROWSTRIDE + ccol0 * 16;
    const uint32_t dB = dA + ASTAGE_BYTES;

    uint32_t aoff[2];
    #pragma unroll
    for (int m = 0; m < 2; ++m)
        aoff[m] = (warp_m * 32 + m * 16 + (l & 15)) * ROWSTRIDE + (l >> 4) * 16;
    uint32_t boff[4];
    {
        int grp = l >> 3, nof = (grp >> 1) * 8 + (l & 7), cof = (grp & 1) * 16;
        #pragma unroll
        for (int p = 0; p < 4; ++p)
            boff[p] = ASTAGE_BYTES + (warp_n * 64 + p * 16 + nof) * ROWSTRIDE + cof;
    }

    #pragma unroll
    for (int it = 0; it < 2; ++it) {
        uint32_t so = sbase + it * STAGE_BYTES;
        const char* sa = srcA + it * 64;
        const char* sb = srcB + it * 64;
        CP16(so + dA, sa); CP16(so + dA + 16, sa + 16);
        CP16(so + dB, sb); CP16(so + dB + 16, sb + 16);
        CP_COMMIT();
    }

    float d[2][8][4];
    #pragma unroll
    for (int m = 0; m < 2; ++m)
        #pragma unroll
        for (int n = 0; n < 8; ++n)
            #pragma unroll
            for (int q = 0; q < 4; ++q) d[m][n][q] = 0.f;

    for (int it = 0; it < NITER; ++it) {
        if (it == NITER - 1) asm volatile("cp.async.wait_group 0;" ::: "memory");
        else                 asm volatile("cp.async.wait_group 1;" ::: "memory");
        __syncthreads();
        uint32_t sb = sbase + (it % 3) * STAGE_BYTES;

        uint32_t a0[2][4], a1[2][4], b0[8][2], b1[8][2];
        #pragma unroll
        for (int m = 0; m < 2; ++m) ldmx4(a0[m], sb + aoff[m]);
        #pragma unroll
        for (int p = 0; p < 4; ++p) {
            uint32_t r[4];
            ldmx4(r, sb + boff[p]);
            b0[2*p][0] = r[0]; b0[2*p][1] = r[1];
            b0[2*p+1][0] = r[2]; b0[2*p+1][1] = r[3];
        }
        #pragma unroll
        for (int m = 0; m < 2; ++m) ldmx4(a1[m], sb + aoff[m] + 32);
        #pragma unroll
        for (int p = 0; p < 4; ++p) {
            uint32_t r[4];
            ldmx4(r, sb + boff[p] + 32);
            b1[2*p][0] = r[0]; b1[2*p][1] = r[1];
            b1[2*p+1][0] = r[2]; b1[2*p+1][1] = r[3];
        }

        if (it + 2 < NITER) {
            uint32_t so = sbase + ((it + 2) % 3) * STAGE_BYTES;
            const char* sa = srcA + (it + 2) * 64;
            const char* sb2 = srcB + (it + 2) * 64;
            CP16(so + dA, sa); CP16(so + dA + 16, sa + 16);
            CP16(so + dB, sb2); CP16(so + dB + 16, sb2 + 16);
            CP_COMMIT();
        }

        #pragma unroll
        for (int m = 0; m < 2; ++m)
            #pragma unroll
            for (int n = 0; n < 8; ++n) mma16816(d[m][n], a0[m], b0[n]);
        #pragma unroll
        for (int m = 0; m < 2; ++m)
            #pragma unroll
            for (int n = 0; n < 8; ++n) mma16816(d[m][n], a1[m], b1[n]);
    }

    // ---- epilogue: exp, direct upper-tile stores, row+col partials (no stage) ----
    __syncthreads();
    float* spart = reinterpret_cast<float*>(smem);          // [128][2] row partials
    float* scol  = reinterpret_cast<float*>(smem) + 256;    // [4][128] col partials

    float sqi[4];
    #pragma unroll
    for (int m = 0; m < 2; ++m)
        #pragma unroll
        for (int h = 0; h < 2; ++h)
            sqi[2*m+h] = g_sq[b * Sdim + by * BM + warp_m * 32 + m * 16 + h * 8 + (l >> 2)];
    float2 sqj[8];
    #pragma unroll
    for (int n = 0; n < 8; ++n)
        sqj[n] = *reinterpret_cast<const float2*>(
            &g_sq[b * Sdim + bx * BN + warp_n * 64 + n * 8 + 2 * (l & 3)]);

    float* ob = out + ((size_t)b * Sdim + by * BM) * Sdim + bx * BN;
    float rs[4] = {0.f, 0.f, 0.f, 0.f};
    float cs[8][2];
    #pragma unroll
    for (int n = 0; n < 8; ++n) { cs[n][0] = 0.f; cs[n][1] = 0.f; }

    #pragma unroll
    for (int m = 0; m < 2; ++m) {
        #pragma unroll
        for (int h = 0; h < 2; ++h) {
            int row = warp_m * 32 + m * 16 + h * 8 + (l >> 2);
            float bi = -0.0625f * sqi[2*m+h];
            float* orow = ob + (size_t)row * Sdim + warp_n * 64 + 2 * (l & 3);
            float acc = 0.f;
            #pragma unroll
            for (int n = 0; n < 8; ++n) {
                float p0 = __expf(fmaf(d[m][n][2*h],     0.125f, fmaf(sqj[n].x, -0.0625f, bi)));
                float p1 = __expf(fmaf(d[m][n][2*h + 1], 0.125f, fmaf(sqj[n].y, -0.0625f, bi)));
                acc += p0 + p1;
                cs[n][0] += p0; cs[n][1] += p1;
                *reinterpret_cast<float2*>(orow + n * 8) = make_float2(p0, p1);
            }
            rs[2*m+h] = acc;
        }
    }
    // row partials
    #pragma unroll
    for (int i = 0; i < 4; ++i) {
        rs[i] += __shfl_xor_sync(0xffffffffu, rs[i], 1);
        rs[i] += __shfl_xor_sync(0xffffffffu, rs[i], 2);
    }
    if ((l & 3) == 0) {
        #pragma unroll
        for (int m = 0; m < 2; ++m)
            #pragma unroll
            for (int h = 0; h < 2; ++h) {
                int row = warp_m * 32 + m * 16 + h * 8 + (l >> 2);
                spart[row * 2 + warp_n] = rs[2*m+h];
            }
    }
    // col partials (for the mirrored rows' sums) — offdiag only
    if (offdiag) {
        #pragma unroll
        for (int n = 0; n < 8; ++n)
            #pragma unroll
            for (int q = 0; q < 2; ++q) {
                cs[n][q] += __shfl_xor_sync(0xffffffffu, cs[n][q], 4);
                cs[n][q] += __shfl_xor_sync(0xffffffffu, cs[n][q], 8);
                cs[n][q] += __shfl_xor_sync(0xffffffffu, cs[n][q], 16);
            }
        if (l < 4) {
            #pragma unroll
            for (int n = 0; n < 8; ++n) {
                int c = warp_n * 64 + n * 8 + 2 * l;
                scol[warp_m * 128 + c]     = cs[n][0];
                scol[warp_m * 128 + c + 1] = cs[n][1];
            }
        }
    }
    __syncthreads();
    if (tid < BM)
        g_part[((size_t)b * Sdim + by * BM + tid) * NPART + bx] =
            spart[tid * 2] + spart[tid * 2 + 1];
    if (offdiag && tid >= 128) {
        int j = tid - 128;
        float s = scol[j] + scol[128 + j] + scol[256 + j] + scol[384 + j];
        g_part[((size_t)b * Sdim + bx * BN + j) * NPART + by] = s;
    }
}

// ================= Kernel 3: tile-level normalize + mirror =================
__global__ __launch_bounds__(256) void norm2_kernel(float* __restrict__ out) {
    extern __shared__ char smem[];
    float* sinv_a = reinterpret_cast<float*>(smem);         // [128] by-rows
    float* sinv_b = sinv_a + 128;                           // [128] bx-rows
    float* stage  = sinv_a + 256;                           // [128][S2]

    const int tid = threadIdx.x;
    const int b = blockIdx.z;
    int by = 0, rem = blockIdx.x;
    while (rem >= NPART - by) { rem -= NPART - by; ++by; }
    const int bx = by + rem;

    // inline inverse row sums (fixed-order, deterministic)
    {
        int rb = (tid < 128) ? by : bx;
        int r  = tid & 127;
        const float* pp = &g_part[((size_t)b * Sdim + rb * BM + r) * NPART];
        float s = 0.f;
        #pragma unroll
        for (int k = 0; k < NPART; ++k) s += pp[k];
        if (tid < 128) sinv_a[r] = 1.0f / s;
        else           sinv_b[r] = 1.0f / s;
    }
    __syncthreads();

    float* obD = out + ((size_t)b * Sdim + by * BM) * Sdim + bx * BN;

    if (bx == by) {
        // diagonal: scale in place
        #pragma unroll 4
        for (int it = 0; it < 16; ++it) {
            int idx = tid + 256 * it;
            int r = idx >> 5, c4 = idx & 31;
            float4* p = reinterpret_cast<float4*>(obD + (size_t)r * Sdim) + c4;
            float4 v = *p;
            float s = sinv_a[r];
            v.x *= s; v.y *= s; v.z *= s; v.w *= s;
            *p = v;
        }
        return;
    }

    // pass 1: read tile, write scaled in place, stash transposed in smem
    #pragma unroll 4
    for (int it = 0; it < 16; ++it) {
        int idx = tid + 256 * it;
        int r = idx >> 5, c4 = idx & 31;
        float4* p = reinterpret_cast<float4*>(obD + (size_t)r * Sdim) + c4;
        float4 v = *p;
        float s = sinv_a[r];
        float4 w = v;
        w.x *= s; w.y *= s; w.z *= s; w.w *= s;
        *p = w;
        // stage[col*S2 + row] = T[row][col] (unnormalized)
        stage[(4 * c4 + 0) * S2 + r] = v.x;
        stage[(4 * c4 + 1) * S2 + r] = v.y;
        stage[(4 * c4 + 2) * S2 + r] = v.z;
        stage[(4 * c4 + 3) * S2 + r] = v.w;
    }
    __syncthreads();

    // pass 2: write mirrored tile, coalesced
    float* obT = out + ((size_t)b * Sdim + bx * BN) * Sdim + by * BM;
    #pragma unroll 4
    for (int it = 0; it < 16; ++it) {
        int idx = tid + 256 * it;
        int j = idx >> 5, c4 = idx & 31;
        float s = sinv_b[j];
        const float* sp = stage + j * S2 + 4 * c4;
        float4 v = make_float4(sp[0] * s, sp[1] * s, sp[2] * s, sp[3] * s);
        *(reinterpret_cast<float4*>(obT + (size_t)j * Sdim) + c4) = v;
    }
}

extern "C" void kernel_launch(void* const* d_in, const int* in_sizes, int n_in,
                              void* d_out, int out_size) {
    const float* x  = (const float*)d_in[0];
    float*       out = (float*)d_out;

    cudaFuncSetAttribute(gemm_kernel,  cudaFuncAttributeMaxDynamicSharedMemorySize, SMEM_MAIN);
    cudaFuncSetAttribute(norm2_kernel, cudaFuncAttributeMaxDynamicSharedMemorySize, NORM_SMEM);

    split_kernel<<<NBATCH * Sdim / 8, 256>>>(x);
    gemm_kernel<<<dim3(NTRI, 1, NBATCH), 256, SMEM_MAIN>>>(out);
    norm2_kernel<<<dim3(NTRI, 1, NBATCH), 256, NORM_SMEM>>>(out);
}

// round 11
// speedup vs baseline: 1.1154x; 1.0248x over previous
#include <cuda_runtime.h>
#include <cuda_bf16.h>
#include <cstdint>

#define Sdim   2048
#define Edim   256
#define KDIM   768                 // virtual K: [hi | lo | hi] · [hi | hi | lo]
#define NBATCH 16
#define BM     128
#define BN     128
#define BK     32
#define NITER  (KDIM / BK)         // 24
#define NPART  (Sdim / BN)         // 16
#define NTRI   (NPART * (NPART + 1) / 2)    // 136 tile pairs per batch
#define ROWSTRIDE 80               // bytes per BK-row in smem: conflict-free ldmatrix
#define ASTAGE_BYTES (BM * ROWSTRIDE)
#define STAGE_BYTES  (2 * BM * ROWSTRIDE)   // A + B = 20480
#define NSTAGE 3
#define SMEM_MAIN (NSTAGE * STAGE_BYTES)    // 61440
#define S2 129                               // norm2 transpose stage stride (floats)
#define NORM_SMEM (1024 + BM * S2 * 4)

// Single-copy hi/lo storage: 16.8 MB each -> whole GEMM operand set is L2-resident.
__device__ __nv_bfloat16 g_hi[(size_t)NBATCH * Sdim * Edim];
__device__ __nv_bfloat16 g_lo[(size_t)NBATCH * Sdim * Edim];
__device__ float         g_sq[NBATCH * Sdim];
__device__ float         g_part[(size_t)NBATCH * Sdim * NPART];

__device__ __forceinline__ uint32_t smem_to_u32(const void* p) {
    uint32_t a;
    asm("{ .reg .u64 t; cvta.to.shared.u64 t, %1; cvt.u32.u64 %0, t; }" : "=r"(a) : "l"(p));
    return a;
}

#define CP16(dst, src) \
    asm volatile("cp.async.cg.shared.global [%0], [%1], 16;" :: "r"(dst), "l"(src) : "memory")
#define CP_COMMIT() asm volatile("cp.async.commit_group;" ::: "memory")

__device__ __forceinline__ void ldmx4(uint32_t* r, uint32_t addr) {
    asm volatile("ldmatrix.sync.aligned.m8n8.x4.shared.b16 {%0,%1,%2,%3}, [%4];"
                 : "=r"(r[0]), "=r"(r[1]), "=r"(r[2]), "=r"(r[3]) : "r"(addr));
}
__device__ __forceinline__ void mma16816(float* d, const uint32_t* a, const uint32_t* b) {
    asm volatile("mma.sync.aligned.m16n8k16.row.col.f32.bf16.bf16.f32 "
                 "{%0,%1,%2,%3}, {%4,%5,%6,%7}, {%8,%9}, {%0,%1,%2,%3};"
                 : "+f"(d[0]), "+f"(d[1]), "+f"(d[2]), "+f"(d[3])
                 : "r"(a[0]), "r"(a[1]), "r"(a[2]), "r"(a[3]), "r"(b[0]), "r"(b[1]));
}

// k-iteration -> source region select (A: hi,lo,hi ; B: hi,hi,lo)
#define SRC_A(p_hi, p_lo, it) (((((it) >> 3) == 1) ? (p_lo) : (p_hi)) + ((it) & 7) * 64)
#define SRC_B(p_hi, p_lo, it) (((((it) >> 3) == 2) ? (p_lo) : (p_hi)) + ((it) & 7) * 64)

// ================= Kernel 1: bf16 hi/lo split + sq norms =================
__global__ __launch_bounds__(256) void split_kernel(const float* __restrict__ x) {
    int row  = blockIdx.x * 8 + (threadIdx.x >> 5);
    int lane = threadIdx.x & 31;
    const float4* xr = reinterpret_cast<const float4*>(x + (size_t)row * Edim);
    float4 v0 = xr[lane], v1 = xr[lane + 32];
    float vv[8] = {v0.x, v0.y, v0.z, v0.w, v1.x, v1.y, v1.z, v1.w};

    float s = 0.f;
    uint32_t ph[4], pl[4];
    #pragma unroll
    for (int q = 0; q < 4; ++q) {
        __nv_bfloat16 h0 = __float2bfloat16(vv[2*q]),   h1 = __float2bfloat16(vv[2*q+1]);
        __nv_bfloat16 l0 = __float2bfloat16(vv[2*q]   - __bfloat162float(h0));
        __nv_bfloat16 l1 = __float2bfloat16(vv[2*q+1] - __bfloat162float(h1));
        __nv_bfloat162 hp = __halves2bfloat162(h0, h1), lp = __halves2bfloat162(l0, l1);
        ph[q] = *reinterpret_cast<uint32_t*>(&hp);
        pl[q] = *reinterpret_cast<uint32_t*>(&lp);
        s += vv[2*q]*vv[2*q] + vv[2*q+1]*vv[2*q+1];
    }
    size_t base = (size_t)row * Edim;
    int c = 4 * lane;
    *reinterpret_cast<uint2*>(&g_hi[base +       c]) = make_uint2(ph[0], ph[1]);
    *reinterpret_cast<uint2*>(&g_hi[base + 128 + c]) = make_uint2(ph[2], ph[3]);
    *reinterpret_cast<uint2*>(&g_lo[base +       c]) = make_uint2(pl[0], pl[1]);
    *reinterpret_cast<uint2*>(&g_lo[base + 128 + c]) = make_uint2(pl[2], pl[3]);

    #pragma unroll
    for (int o = 16; o; o >>= 1) s += __shfl_xor_sync(0xffffffffu, s, o);
    if (lane == 0) g_sq[row] = s;
}

// ================= Kernel 2: HMMA gram + exp, upper-tri tiles only =================
__global__ __launch_bounds__(256, 2) void gemm_kernel(float* __restrict__ out) {
    extern __shared__ char smem[];
    uint32_t sbase = smem_to_u32(smem);
    const int tid = threadIdx.x, l = tid & 31, wid = tid >> 5;
    const int warp_m = wid & 3, warp_n = wid >> 2;     // 4 x 2 warps, 32x64 tiles
    const int b = blockIdx.z;

    int by = 0, rem = blockIdx.x;
    while (rem >= NPART - by) { rem -= NPART - by; ++by; }
    const int bx = by + rem;
    const bool offdiag = (bx != by);

    // cp.async mapping: thread -> (row crow, 32B half of each 64B k-chunk)
    const int crow = tid >> 1;
    const char* pAh = (const char*)(g_hi + ((size_t)b * Sdim + by * BM + crow) * Edim) + (tid & 1) * 32;
    const char* pAl = (const char*)(g_lo + ((size_t)b * Sdim + by * BM + crow) * Edim) + (tid & 1) * 32;
    const char* pBh = (const char*)(g_hi + ((size_t)b * Sdim + bx * BN + crow) * Edim) + (tid & 1) * 32;
    const char* pBl = (const char*)(g_lo + ((size_t)b * Sdim + bx * BN + crow) * Edim) + (tid & 1) * 32;
    const uint32_t dA = crow * ROWSTRIDE + (tid & 1) * 32;
    const uint32_t dB = dA + ASTAGE_BYTES;

    uint32_t aoff[2];
    #pragma unroll
    for (int m = 0; m < 2; ++m)
        aoff[m] = (warp_m * 32 + m * 16 + (l & 15)) * ROWSTRIDE + (l >> 4) * 16;
    uint32_t boff[4];
    {
        int grp = l >> 3, nof = (grp >> 1) * 8 + (l & 7), cof = (grp & 1) * 16;
        #pragma unroll
        for (int p = 0; p < 4; ++p)
            boff[p] = ASTAGE_BYTES + (warp_n * 64 + p * 16 + nof) * ROWSTRIDE + cof;
    }

    #pragma unroll
    for (int it = 0; it < 2; ++it) {               // it < 8: both read hi
        uint32_t so = sbase + it * STAGE_BYTES;
        const char* sa = pAh + it * 64;
        const char* sb = pBh + it * 64;
        CP16(so + dA, sa); CP16(so + dA + 16, sa + 16);
        CP16(so + dB, sb); CP16(so + dB + 16, sb + 16);
        CP_COMMIT();
    }

    float d[2][8][4];
    #pragma unroll
    for (int m = 0; m < 2; ++m)
        #pragma unroll
        for (int n = 0; n < 8; ++n)
            #pragma unroll
            for (int q = 0; q < 4; ++q) d[m][n][q] = 0.f;

    for (int it = 0; it < NITER; ++it) {
        if (it == NITER - 1) asm volatile("cp.async.wait_group 0;" ::: "memory");
        else                 asm volatile("cp.async.wait_group 1;" ::: "memory");
        __syncthreads();
        uint32_t sb = sbase + (it % 3) * STAGE_BYTES;

        // ---- ks = 0: load fragments ----
        uint32_t a0[2][4], b0[8][2];
        #pragma unroll
        for (int m = 0; m < 2; ++m) ldmx4(a0[m], sb + aoff[m]);
        #pragma unroll
        for (int p = 0; p < 4; ++p) {
            uint32_t r[4];
            ldmx4(r, sb + boff[p]);
            b0[2*p][0] = r[0]; b0[2*p][1] = r[1];
            b0[2*p+1][0] = r[2]; b0[2*p+1][1] = r[3];
        }
        // prefetch next stage early (independent of fragments)
        if (it + 2 < NITER) {
            int itp = it + 2;
            uint32_t so = sbase + (itp % 3) * STAGE_BYTES;
            const char* sa = SRC_A(pAh, pAl, itp);
            const char* sb2 = SRC_B(pBh, pBl, itp);
            CP16(so + dA, sa); CP16(so + dA + 16, sa + 16);
            CP16(so + dB, sb2); CP16(so + dB + 16, sb2 + 16);
            CP_COMMIT();
        }
        #pragma unroll
        for (int m = 0; m < 2; ++m)
            #pragma unroll
            for (int n = 0; n < 8; ++n) mma16816(d[m][n], a0[m], b0[n]);

        // ---- ks = 1 ----
        uint32_t a1[2][4], b1[8][2];
        #pragma unroll
        for (int m = 0; m < 2; ++m) ldmx4(a1[m], sb + aoff[m] + 32);
        #pragma unroll
        for (int p = 0; p < 4; ++p) {
            uint32_t r[4];
            ldmx4(r, sb + boff[p] + 32);
            b1[2*p][0] = r[0]; b1[2*p][1] = r[1];
            b1[2*p+1][0] = r[2]; b1[2*p+1][1] = r[3];
        }
        #pragma unroll
        for (int m = 0; m < 2; ++m)
            #pragma unroll
            for (int n = 0; n < 8; ++n) mma16816(d[m][n], a1[m], b1[n]);
    }

    // ---- epilogue: exp, direct upper-tile stores, row+col partials ----
    __syncthreads();
    float* spart = reinterpret_cast<float*>(smem);          // [128][2] row partials
    float* scol  = reinterpret_cast<float*>(smem) + 256;    // [4][128] col partials

    float sqi[4];
    #pragma unroll
    for (int m = 0; m < 2; ++m)
        #pragma unroll
        for (int h = 0; h < 2; ++h)
            sqi[2*m+h] = g_sq[b * Sdim + by * BM + warp_m * 32 + m * 16 + h * 8 + (l >> 2)];
    float2 sqj[8];
    #pragma unroll
    for (int n = 0; n < 8; ++n)
        sqj[n] = *reinterpret_cast<const float2*>(
            &g_sq[b * Sdim + bx * BN + warp_n * 64 + n * 8 + 2 * (l & 3)]);

    float* ob = out + ((size_t)b * Sdim + by * BM) * Sdim + bx * BN;
    float rs[4] = {0.f, 0.f, 0.f, 0.f};
    float cs[8][2];
    #pragma unroll
    for (int n = 0; n < 8; ++n) { cs[n][0] = 0.f; cs[n][1] = 0.f; }

    #pragma unroll
    for (int m = 0; m < 2; ++m) {
        #pragma unroll
        for (int h = 0; h < 2; ++h) {
            int row = warp_m * 32 + m * 16 + h * 8 + (l >> 2);
            float bi = -0.0625f * sqi[2*m+h];
            float* orow = ob + (size_t)row * Sdim + warp_n * 64 + 2 * (l & 3);
            float acc = 0.f;
            #pragma unroll
            for (int n = 0; n < 8; ++n) {
                float p0 = __expf(fmaf(d[m][n][2*h],     0.125f, fmaf(sqj[n].x, -0.0625f, bi)));
                float p1 = __expf(fmaf(d[m][n][2*h + 1], 0.125f, fmaf(sqj[n].y, -0.0625f, bi)));
                acc += p0 + p1;
                cs[n][0] += p0; cs[n][1] += p1;
                *reinterpret_cast<float2*>(orow + n * 8) = make_float2(p0, p1);
            }
            rs[2*m+h] = acc;
        }
    }
    #pragma unroll
    for (int i = 0; i < 4; ++i) {
        rs[i] += __shfl_xor_sync(0xffffffffu, rs[i], 1);
        rs[i] += __shfl_xor_sync(0xffffffffu, rs[i], 2);
    }
    if ((l & 3) == 0) {
        #pragma unroll
        for (int m = 0; m < 2; ++m)
            #pragma unroll
            for (int h = 0; h < 2; ++h) {
                int row = warp_m * 32 + m * 16 + h * 8 + (l >> 2);
                spart[row * 2 + warp_n] = rs[2*m+h];
            }
    }
    if (offdiag) {
        #pragma unroll
        for (int n = 0; n < 8; ++n)
            #pragma unroll
            for (int q = 0; q < 2; ++q) {
                cs[n][q] += __shfl_xor_sync(0xffffffffu, cs[n][q], 4);
                cs[n][q] += __shfl_xor_sync(0xffffffffu, cs[n][q], 8);
                cs[n][q] += __shfl_xor_sync(0xffffffffu, cs[n][q], 16);
            }
        if (l < 4) {
            #pragma unroll
            for (int n = 0; n < 8; ++n) {
                int c = warp_n * 64 + n * 8 + 2 * l;
                scol[warp_m * 128 + c]     = cs[n][0];
                scol[warp_m * 128 + c + 1] = cs[n][1];
            }
        }
    }
    __syncthreads();
    if (tid < BM)
        g_part[((size_t)b * Sdim + by * BM + tid) * NPART + bx] =
            spart[tid * 2] + spart[tid * 2 + 1];
    if (offdiag && tid >= 128) {
        int j = tid - 128;
        float s = scol[j] + scol[128 + j] + scol[256 + j] + scol[384 + j];
        g_part[((size_t)b * Sdim + bx * BN + j) * NPART + by] = s;
    }
}

// ================= Kernel 3: tile-level normalize + mirror =================
__global__ __launch_bounds__(256) void norm2_kernel(float* __restrict__ out) {
    extern __shared__ char smem[];
    float* sinv_a = reinterpret_cast<float*>(smem);         // [128] by-rows
    float* sinv_b = sinv_a + 128;                           // [128] bx-rows
    float* stage  = sinv_a + 256;                           // [128][S2]

    const int tid = threadIdx.x;
    const int b = blockIdx.z;
    int by = 0, rem = blockIdx.x;
    while (rem >= NPART - by) { rem -= NPART - by; ++by; }
    const int bx = by + rem;

    {
        int rb = (tid < 128) ? by : bx;
        int r  = tid & 127;
        const float* pp = &g_part[((size_t)b * Sdim + rb * BM + r) * NPART];
        float s = 0.f;
        #pragma unroll
        for (int k = 0; k < NPART; ++k) s += pp[k];
        if (tid < 128) sinv_a[r] = 1.0f / s;
        else           sinv_b[r] = 1.0f / s;
    }
    __syncthreads();

    float* obD = out + ((size_t)b * Sdim + by * BM) * Sdim + bx * BN;

    if (bx == by) {
        #pragma unroll 4
        for (int it = 0; it < 16; ++it) {
            int idx = tid + 256 * it;
            int r = idx >> 5, c4 = idx & 31;
            float4* p = reinterpret_cast<float4*>(obD + (size_t)r * Sdim) + c4;
            float4 v = *p;
            float s = sinv_a[r];
            v.x *= s; v.y *= s; v.z *= s; v.w *= s;
            *p = v;
        }
        return;
    }

    #pragma unroll 4
    for (int it = 0; it < 16; ++it) {
        int idx = tid + 256 * it;
        int r = idx >> 5, c4 = idx & 31;
        float4* p = reinterpret_cast<float4*>(obD + (size_t)r * Sdim) + c4;
        float4 v = *p;
        float s = sinv_a[r];
        float4 w = v;
        w.x *= s; w.y *= s; w.z *= s; w.w *= s;
        *p = w;
        stage[(4 * c4 + 0) * S2 + r] = v.x;
        stage[(4 * c4 + 1) * S2 + r] = v.y;
        stage[(4 * c4 + 2) * S2 + r] = v.z;
        stage[(4 * c4 + 3) * S2 + r] = v.w;
    }
    __syncthreads();

    float* obT = out + ((size_t)b * Sdim + bx * BN) * Sdim + by * BM;
    #pragma unroll 4
    for (int it = 0; it < 16; ++it) {
        int idx = tid + 256 * it;
        int j = idx >> 5, c4 = idx & 31;
        float s = sinv_b[j];
        const float* sp = stage + j * S2 + 4 * c4;
        float4 v = make_float4(sp[0] * s, sp[1] * s, sp[2] * s, sp[3] * s);
        *(reinterpret_cast<float4*>(obT + (size_t)j * Sdim) + c4) = v;
    }
}

extern "C" void kernel_launch(void* const* d_in, const int* in_sizes, int n_in,
                              void* d_out, int out_size) {
    const float* x  = (const float*)d_in[0];
    float*       out = (float*)d_out;

    cudaFuncSetAttribute(gemm_kernel,  cudaFuncAttributeMaxDynamicSharedMemorySize, SMEM_MAIN);
    cudaFuncSetAttribute(norm2_kernel, cudaFuncAttributeMaxDynamicSharedMemorySize, NORM_SMEM);

    split_kernel<<<NBATCH * Sdim / 8, 256>>>(x);
    gemm_kernel<<<dim3(NTRI, 1, NBATCH), 256, SMEM_MAIN>>>(out);
    norm2_kernel<<<dim3(NTRI, 1, NBATCH), 256, NORM_SMEM>>>(out);
}